// round 14
// baseline (speedup 1.0000x reference)
#include <cuda_runtime.h>
#include <cstdint>

// Problem constants.
#define KB 4
#define KS 4096
#define KH 16
#define KD 64
#define KC 128                 // chunk size
#define KN (KS / KC)           // 32 chunks per (b,h)
#define KBH (KB * KH)          // 64
#define KROW (KH * KD)         // 1024 floats between consecutive s

// Smem pitches (words). Bank-conflict-free fragment access patterns:
//  pitch%32==4 with rows indexed by (x+grp), cols by tg  -> 4grp+tg distinct
//  pitch%32==8 with rows indexed by (x+tg),  cols by grp -> 8tg+grp distinct
#define PQ 68      // Qs/Ks [128][PQ]
#define PVH 40     // Vs half [128][PVH], Ps [64][PVH]
#define PS 132     // Ss [128][PS]

// Smem word offsets
#define QS_W 0
#define KS_W (QS_W + 128 * PQ)          // 8704
#define VS_W (KS_W + 128 * PQ)          // 17408
#define PS_W (VS_W + 128 * PVH)         // 22528
#define SS_W (PS_W + 64 * PVH)          // 25088
#define SM_WORDS (SS_W + 128 * PS)      // 41984 words = 167936 B

__device__ __forceinline__ unsigned f2tf(float x) {
    unsigned u;
    asm("cvt.rna.tf32.f32 %0, %1;" : "=r"(u) : "f"(x));
    return u;
}

__device__ __forceinline__ void mma_tf32(float* c, const unsigned* a, const unsigned* b) {
    asm volatile(
        "mma.sync.aligned.m16n8k8.row.col.f32.tf32.tf32.f32 "
        "{%0,%1,%2,%3}, {%4,%5,%6,%7}, {%8,%9}, {%0,%1,%2,%3};"
        : "+f"(c[0]), "+f"(c[1]), "+f"(c[2]), "+f"(c[3])
        : "r"(a[0]), "r"(a[1]), "r"(a[2]), "r"(a[3]), "r"(b[0]), "r"(b[1]));
}

// ---------------------------------------------------------------------------
// Fused persistent kernel: one CTA per (b, h, e-half). Walks 32 chunks
// sequentially, keeping KV state P[64][32] in shared memory.
// Per chunk: S = Q K^T (causal), O = tril(S) V_half + Q P, P += K^T V_half.
// ---------------------------------------------------------------------------
__global__ __launch_bounds__(256) void fused_kernel(const float* __restrict__ Q,
                                                    const float* __restrict__ K,
                                                    const float* __restrict__ V,
                                                    float* __restrict__ O) {
    extern __shared__ unsigned sm[];
    unsigned* Qs = sm + QS_W;             // [128][PQ]   Q[i][d], tf32
    unsigned* Ks = sm + KS_W;             // [128][PQ]   K[j][d], tf32
    unsigned* Vs = sm + VS_W;             // [128][PVH]  V[j][e_local], tf32
    float*    Ps = (float*)(sm + PS_W);   // [64][PVH]   P[d][e_local], fp32 state
    unsigned* Ss = sm + SS_W;             // [128][PS]   masked S, tf32

    const int cta = blockIdx.x;
    const int bh = cta >> 1;
    const int eh = cta & 1;               // e-half: 0 or 1
    const int b = bh >> 4;
    const int h = bh & 15;
    const int e0g = eh << 5;              // global e offset of this half

    const int tid = threadIdx.x;
    const int wid = tid >> 5;
    const int lane = tid & 31;
    const int grp = lane >> 2;
    const int tg = lane & 3;

    // Zero the KV state and (once) the whole Ss buffer. Upper-triangular
    // tiles of Ss are never written again; they stay zero across all chunks.
#pragma unroll
    for (int t = tid; t < 64 * PVH; t += 256) Ps[t] = 0.0f;
#pragma unroll
    for (int t = tid; t < 128 * PS; t += 256) Ss[t] = 0u;
    __syncthreads();

    // Warp tilings (fixed across chunks)
    const int wm1 = (wid >> 1) << 5;      // stage1: S rows   (32x64 tiles, 4x2)
    const int wn1 = (wid & 1) << 6;       // stage1: S cols
    const bool s1_live = (wn1 <= wm1 + 31);
    const int wm = (wid >> 1) << 5;       // stage2: O rows   (32x16 tiles, 4x2)
    const int wn = (wid & 1) << 4;        // stage2: O cols (local e)
    const int wmp = (wid >> 1) << 4;      // kv-update: P rows (16x16 tiles, 4x2)
    const int wnp = (wid & 1) << 4;       // kv-update: P cols (local e)

    for (int n = 0; n < KN; ++n) {
        const int base = ((b * KS + n * KC) * KH + h) * KD;

        // ---- Load Q, K (full 128x64) and V (half: 128x32) as tf32 ----
#pragma unroll
        for (int t = tid; t < 128 * 16; t += 256) {
            const int row = t >> 4;
            const int col = (t & 15) << 2;
            const int ga = base + row * KROW + col;
            const float4 qq = *(const float4*)&Q[ga];
            *(uint4*)&Qs[row * PQ + col] =
                make_uint4(f2tf(qq.x), f2tf(qq.y), f2tf(qq.z), f2tf(qq.w));
            const float4 kk = *(const float4*)&K[ga];
            *(uint4*)&Ks[row * PQ + col] =
                make_uint4(f2tf(kk.x), f2tf(kk.y), f2tf(kk.z), f2tf(kk.w));
        }
#pragma unroll
        for (int t = tid; t < 128 * 8; t += 256) {
            const int row = t >> 3;
            const int col = (t & 7) << 2;
            const float4 vv = *(const float4*)&V[base + row * KROW + e0g + col];
            *(uint4*)&Vs[row * PVH + col] =
                make_uint4(f2tf(vv.x), f2tf(vv.y), f2tf(vv.z), f2tf(vv.w));
        }
        __syncthreads();

        // ---- Stage 1: S = Q K^T (128x128x64), causal-skipped tiles idle ----
        if (s1_live) {
            float acc[2][8][4];
#pragma unroll
            for (int mi = 0; mi < 2; ++mi)
#pragma unroll
                for (int ni = 0; ni < 8; ++ni)
#pragma unroll
                    for (int r = 0; r < 4; ++r) acc[mi][ni][r] = 0.0f;

#pragma unroll
            for (int d0 = 0; d0 < KD; d0 += 8) {
                unsigned a[2][4], bb[8][2];
#pragma unroll
                for (int mi = 0; mi < 2; ++mi) {
                    const int i = wm1 + (mi << 4);
                    a[mi][0] = Qs[(i + grp) * PQ + d0 + tg];
                    a[mi][1] = Qs[(i + grp + 8) * PQ + d0 + tg];
                    a[mi][2] = Qs[(i + grp) * PQ + d0 + tg + 4];
                    a[mi][3] = Qs[(i + grp + 8) * PQ + d0 + tg + 4];
                }
#pragma unroll
                for (int ni = 0; ni < 8; ++ni) {
                    const int j = wn1 + (ni << 3) + grp;
                    bb[ni][0] = Ks[j * PQ + d0 + tg];
                    bb[ni][1] = Ks[j * PQ + d0 + tg + 4];
                }
#pragma unroll
                for (int mi = 0; mi < 2; ++mi)
#pragma unroll
                    for (int ni = 0; ni < 8; ++ni) mma_tf32(acc[mi][ni], a[mi], bb[ni]);
            }

            // Mask (j<=i), store tf32 to Ss[i][j].
#pragma unroll
            for (int mi = 0; mi < 2; ++mi)
#pragma unroll
                for (int ni = 0; ni < 8; ++ni) {
                    const int i0r = wm1 + (mi << 4) + grp;
                    const int jc = wn1 + (ni << 3) + (tg << 1);
                    Ss[i0r * PS + jc]     = (jc     <= i0r) ? f2tf(acc[mi][ni][0]) : 0u;
                    Ss[i0r * PS + jc + 1] = (jc + 1 <= i0r) ? f2tf(acc[mi][ni][1]) : 0u;
                    Ss[(i0r + 8) * PS + jc]     = (jc     <= i0r + 8) ? f2tf(acc[mi][ni][2]) : 0u;
                    Ss[(i0r + 8) * PS + jc + 1] = (jc + 1 <= i0r + 8) ? f2tf(acc[mi][ni][3]) : 0u;
                }
        }
        __syncthreads();

        // ---- Stage 2: O = Ss V_half + Q P  (128x32), warp tile 32x16 ----
        {
            float acc[2][2][4];
#pragma unroll
            for (int mi = 0; mi < 2; ++mi)
#pragma unroll
                for (int ni = 0; ni < 2; ++ni)
#pragma unroll
                    for (int r = 0; r < 4; ++r) acc[mi][ni][r] = 0.0f;

            // 2a: sum over j; S rows [wm,wm+32) have zeros beyond j=wm+31.
            const int jmax = wm + 32;
#pragma unroll 4
            for (int j0 = 0; j0 < jmax; j0 += 8) {
                unsigned a[2][4], bb[2][2];
#pragma unroll
                for (int mi = 0; mi < 2; ++mi) {
                    const int i = wm + (mi << 4);
                    a[mi][0] = Ss[(i + grp) * PS + j0 + tg];
                    a[mi][1] = Ss[(i + grp + 8) * PS + j0 + tg];
                    a[mi][2] = Ss[(i + grp) * PS + j0 + tg + 4];
                    a[mi][3] = Ss[(i + grp + 8) * PS + j0 + tg + 4];
                }
#pragma unroll
                for (int ni = 0; ni < 2; ++ni) {
                    const int e = wn + (ni << 3) + grp;
                    bb[ni][0] = Vs[(j0 + tg) * PVH + e];
                    bb[ni][1] = Vs[(j0 + tg + 4) * PVH + e];
                }
#pragma unroll
                for (int mi = 0; mi < 2; ++mi)
#pragma unroll
                    for (int ni = 0; ni < 2; ++ni) mma_tf32(acc[mi][ni], a[mi], bb[ni]);
            }

            // 2b: sum over d (64) against the fp32 state P (rna-convert on read).
#pragma unroll
            for (int d0 = 0; d0 < KD; d0 += 8) {
                unsigned a[2][4], bb[2][2];
#pragma unroll
                for (int mi = 0; mi < 2; ++mi) {
                    const int i = wm + (mi << 4);
                    a[mi][0] = Qs[(i + grp) * PQ + d0 + tg];
                    a[mi][1] = Qs[(i + grp + 8) * PQ + d0 + tg];
                    a[mi][2] = Qs[(i + grp) * PQ + d0 + tg + 4];
                    a[mi][3] = Qs[(i + grp + 8) * PQ + d0 + tg + 4];
                }
#pragma unroll
                for (int ni = 0; ni < 2; ++ni) {
                    const int e = wn + (ni << 3) + grp;
                    bb[ni][0] = f2tf(Ps[(d0 + tg) * PVH + e]);
                    bb[ni][1] = f2tf(Ps[(d0 + tg + 4) * PVH + e]);
                }
#pragma unroll
                for (int mi = 0; mi < 2; ++mi)
#pragma unroll
                    for (int ni = 0; ni < 2; ++ni) mma_tf32(acc[mi][ni], a[mi], bb[ni]);
            }

            // Store this half of O.
#pragma unroll
            for (int mi = 0; mi < 2; ++mi)
#pragma unroll
                for (int ni = 0; ni < 2; ++ni) {
                    const int i = wm + (mi << 4) + grp;
                    const int e = e0g + wn + (ni << 3) + (tg << 1);
                    *(float2*)&O[base + i * KROW + e] =
                        make_float2(acc[mi][ni][0], acc[mi][ni][1]);
                    *(float2*)&O[base + (i + 8) * KROW + e] =
                        make_float2(acc[mi][ni][2], acc[mi][ni][3]);
                }
        }
        __syncthreads();   // stage2b P reads complete before P update

        // ---- KV-state update: P += K^T V_half (64x32x128), warp tile 16x16 ----
        {
            float accp[2][4];
#pragma unroll
            for (int ni = 0; ni < 2; ++ni)
#pragma unroll
                for (int r = 0; r < 4; ++r) accp[ni][r] = 0.0f;

#pragma unroll
            for (int k0 = 0; k0 < KC; k0 += 8) {
                unsigned a[4], bb[2][2];
                // A[m=d][k=j] = K[j][d] read straight from row-major Ks.
                a[0] = Ks[(k0 + tg) * PQ + wmp + grp];
                a[1] = Ks[(k0 + tg) * PQ + wmp + grp + 8];
                a[2] = Ks[(k0 + tg + 4) * PQ + wmp + grp];
                a[3] = Ks[(k0 + tg + 4) * PQ + wmp + grp + 8];
#pragma unroll
                for (int ni = 0; ni < 2; ++ni) {
                    const int e = wnp + (ni << 3) + grp;
                    bb[ni][0] = Vs[(k0 + tg) * PVH + e];
                    bb[ni][1] = Vs[(k0 + tg + 4) * PVH + e];
                }
#pragma unroll
                for (int ni = 0; ni < 2; ++ni) mma_tf32(accp[ni], a, bb[ni]);
            }

#pragma unroll
            for (int ni = 0; ni < 2; ++ni) {
                const int d = wmp + grp;
                const int e = wnp + (ni << 3) + (tg << 1);
                Ps[d * PVH + e]     += accp[ni][0];
                Ps[d * PVH + e + 1] += accp[ni][1];
                Ps[(d + 8) * PVH + e]     += accp[ni][2];
                Ps[(d + 8) * PVH + e + 1] += accp[ni][3];
            }
        }
        __syncthreads();   // P updated & K/V reads done before next chunk load
    }
}

// ---------------------------------------------------------------------------
// Launch: single persistent kernel, 128 CTAs (64 bh x 2 e-halves).
// ---------------------------------------------------------------------------
static const int kSmem = SM_WORDS * (int)sizeof(unsigned);   // 167936 B

extern "C" void kernel_launch(void* const* d_in, const int* in_sizes, int n_in,
                              void* d_out, int out_size) {
    const float* q = (const float*)d_in[0];
    const float* k = (const float*)d_in[1];
    const float* v = (const float*)d_in[2];
    float* out = (float*)d_out;

    cudaFuncSetAttribute(fused_kernel, cudaFuncAttributeMaxDynamicSharedMemorySize,
                         kSmem);
    fused_kernel<<<KBH * 2, 256, kSmem>>>(q, k, v, out);
}